// round 1
// baseline (speedup 1.0000x reference)
#include <cuda_runtime.h>

// Lorenz96, 100 steps of Kutta-3/8 RK4, dt=0.01, F=8.
// Layout: 8 lanes per row, 5 contiguous elements per lane (40 = 8*5).
// Cyclic neighbor access via __shfl_sync with width=8 (segment wrap == row wrap).
// State lives entirely in registers across all 100 steps; gmem touched only at
// load/store (80 MB total, ~10us — irrelevant). Pure fp32 FMA-pipe kernel.

#define L96_DIM   40
#define L96_EPL   5     // elements per lane
#define L96_LPR   8     // lanes per row
#define L96_STEPS 100

__device__ __forceinline__ void l96_rhs(const float src[L96_EPL], float dst[L96_EPL], int sub) {
    const unsigned m = 0xffffffffu;
    // halo: left neighbor's last two elems, right neighbor's first elem (cyclic in 8-lane group)
    float ym2 = __shfl_sync(m, src[3], sub + 7, L96_LPR);  // y[i0-2]
    float ym1 = __shfl_sync(m, src[4], sub + 7, L96_LPR);  // y[i0-1]
    float yp1 = __shfl_sync(m, src[0], sub + 1, L96_LPR);  // y[i0+5]
    const float F = 8.0f;
    float k0 = fmaf(src[1] - ym2,    ym1,    F - src[0]);
    float k1 = fmaf(src[2] - ym1,    src[0], F - src[1]);
    float k2 = fmaf(src[3] - src[0], src[1], F - src[2]);
    float k3 = fmaf(src[4] - src[1], src[2], F - src[3]);
    float k4 = fmaf(yp1    - src[2], src[3], F - src[4]);
    dst[0] = k0; dst[1] = k1; dst[2] = k2; dst[3] = k3; dst[4] = k4;
}

__global__ void __launch_bounds__(256)
lorenz96_kernel(const float* __restrict__ x_in, float* __restrict__ x_out, int batch) {
    int tid = blockIdx.x * blockDim.x + threadIdx.x;
    int row = tid >> 3;         // tid / 8
    int sub = tid & 7;          // lane within row group
    if (row >= batch) return;   // exact division in practice; whole warps exit together

    const float DT  = 0.01f;
    const float DT3 = DT / 3.0f;
    const float DT8 = DT / 8.0f;

    const float* xp = x_in  + (size_t)row * L96_DIM + sub * L96_EPL;
    float*       op = x_out + (size_t)row * L96_DIM + sub * L96_EPL;

    float x[L96_EPL], y[L96_EPL], a[L96_EPL], s[L96_EPL];
    #pragma unroll
    for (int i = 0; i < L96_EPL; i++) x[i] = xp[i];

    #pragma unroll 1
    for (int step = 0; step < L96_STEPS; step++) {
        // ---- stage 1: k1 = f(x) ----
        l96_rhs(x, y, sub);                 // y = k1
        #pragma unroll
        for (int i = 0; i < L96_EPL; i++) {
            float t = y[i];
            s[i] = t;                       // s = k1
            a[i] = t;                       // a = k1
            y[i] = fmaf(DT3, t, x[i]);      // y2 = x + (dt/3)*k1
        }
        // ---- stage 2: k2 = f(y2) ----
        l96_rhs(y, y, sub);                 // y = k2
        #pragma unroll
        for (int i = 0; i < L96_EPL; i++) {
            float t = y[i];
            y[i] = fmaf(DT, t, fmaf(-DT3, a[i], x[i]));  // y3 = x + dt*k2 - (dt/3)*k1
            s[i] = fmaf(3.0f, t, s[i]);     // s = k1 + 3*k2
            a[i] -= t;                      // a = k1 - k2
        }
        // ---- stage 3: k3 = f(y3) ----
        l96_rhs(y, y, sub);                 // y = k3
        #pragma unroll
        for (int i = 0; i < L96_EPL; i++) {
            float t = y[i];
            s[i] = fmaf(3.0f, t, s[i]);     // s = k1 + 3*k2 + 3*k3
            y[i] = fmaf(DT, a[i] + t, x[i]);// y4 = x + dt*(k1 - k2 + k3)
        }
        // ---- stage 4: k4 = f(y4) ----
        l96_rhs(y, y, sub);                 // y = k4
        #pragma unroll
        for (int i = 0; i < L96_EPL; i++) {
            x[i] = fmaf(DT8, s[i] + y[i], x[i]);  // x += dt*(k1+3k2+3k3+k4)/8
        }
    }

    #pragma unroll
    for (int i = 0; i < L96_EPL; i++) op[i] = x[i];
}

extern "C" void kernel_launch(void* const* d_in, const int* in_sizes, int n_in,
                              void* d_out, int out_size) {
    const float* x = (const float*)d_in[0];
    float* out = (float*)d_out;
    int batch = in_sizes[0] / L96_DIM;          // 262144
    int total_threads = batch * L96_LPR;        // 8 lanes per row
    int block = 256;
    int grid = (total_threads + block - 1) / block;
    lorenz96_kernel<<<grid, block>>>(x, out, batch);
}